// round 17
// baseline (speedup 1.0000x reference)
#include <cuda_runtime.h>

#define B_ 4
#define T_ 2048
#define H_ 16
#define D_ 128
#define HD 2048        // H_*D_
#define S_ 16          // steps per chunk
#define NC (T_/S_)     // 128 chunks

// smem float offsets
#define FS 0           // f rows:  16 t * 128 (also provides column f)
#define KS 2048        // kg rows
#define QS 4096        // q rows
#define VG 6144        // vg cols: 16 t * 64
#define PT 7168        // partials: 2 parity * 16 s * (16 rp * 68 = 1088)
#define PT_PAR 17408
#define SM_FLOATS (7168 + 2 * 17408)
#define SM_BYTES  (SM_FLOATS * 4)    // 167936

typedef unsigned long long u64;

__device__ __forceinline__ u64 pk2(float x, float y) {
    u64 r; asm("mov.b64 %0,{%1,%2};" : "=l"(r) : "f"(x), "f"(y)); return r;
}
__device__ __forceinline__ float2 up2(u64 a) {
    float2 r; asm("mov.b64 {%0,%1},%2;" : "=f"(r.x), "=f"(r.y) : "l"(a)); return r;
}
__device__ __forceinline__ u64 mul2(u64 a, u64 b) {
    u64 d; asm("mul.rn.f32x2 %0,%1,%2;" : "=l"(d) : "l"(a), "l"(b)); return d;
}
__device__ __forceinline__ u64 add2(u64 a, u64 b) {
    u64 d; asm("add.rn.f32x2 %0,%1,%2;" : "=l"(d) : "l"(a), "l"(b)); return d;
}
__device__ __forceinline__ u64 fma2(u64 a, u64 b, u64 c) {
    u64 d; asm("fma.rn.f32x2 %0,%1,%2,%3;" : "=l"(d) : "l"(a), "l"(b), "l"(c)); return d;
}
__device__ __forceinline__ u64 max2c(u64 a, float c) {
    float2 t = up2(a);
    t.x = fmaxf(t.x, c); t.y = fmaxf(t.y, c);
    return pk2(t.x, t.y);
}
__device__ __forceinline__ u64 shflx8(u64 x) {   // shfl_xor(8) of a packed pair
    unsigned lo, hi;
    asm("mov.b64 {%0,%1},%2;" : "=r"(lo), "=r"(hi) : "l"(x));
    lo = __shfl_xor_sync(0xffffffffu, lo, 8);
    hi = __shfl_xor_sync(0xffffffffu, hi, 8);
    u64 r; asm("mov.b64 %0,{%1,%2};" : "=l"(r) : "r"(lo), "r"(hi));
    return r;
}

__global__ __launch_bounds__(1024, 1) void delta_kernel(
    const float* __restrict__ q, const float* __restrict__ k,
    const float* __restrict__ v, const float* __restrict__ f,
    const float* __restrict__ g, float* __restrict__ out)
{
    extern __shared__ float smp[];

    const int tid  = threadIdx.x;
    const int w    = tid >> 5, lane = tid & 31;
    const int rt   = w >> 2;            // 8 row-tiles of 16 rows
    const int ctl  = w & 3;             // 4 col-tiles of 16 cols
    const int lr   = lane >> 3;         // 4 row-blocks of 4 rows
    const int lc   = lane & 7;          // 8 col-blocks of 2 cols
    const int colbase = blockIdx.x * 64;
    const long base0  = (long)blockIdx.z * T_ * HD + (long)blockIdx.y * D_;

    const int R0  = rt * 16 + lr * 4;   // my 4 rows
    const int C0  = ctl * 16 + lc * 2;  // my 2 cols (local)
    const int FCI = colbase + C0;       // column f from FS row tile
    const int rp68 = (rt * 2 + (lr >> 1)) * 68;
    const bool stsOK = ((lr & 1) == 0);

    // ---- staging roles: 4 groups of 256 threads ----
    const int grp = tid >> 8, u = tid & 255;
    // rows (grp 0,1,2): 2 granules each: gid = u, u+256
    const int t0 = u >> 5,          rb0 = u & 31;
    const int t1 = (u + 256) >> 5,  rb1 = u & 31;   // (u+256)&31 == u&31
    const long gr0 = base0 + (long)t0 * HD + rb0 * 4;
    const long gr1 = base0 + (long)t1 * HD + rb1 * 4;
    const int  sb0 = t0 * 128 + rb0 * 4;
    const int  sb1 = t1 * 128 + rb1 * 4;
    // cols (grp 3): 1 granule: t = u>>4, cb = u&15
    const int  tc = u >> 4, cb = u & 15;
    const long gc = base0 + (long)tc * HD + colbase + cb * 4;
    const int  cidx = tc * 64 + cb * 4;

    // prefetch chunk 0 (per group)
    float4 pa0, pa1, pb0, pb1;
    if (grp == 0)      { pa0 = *(const float4*)(f + gr0); pa1 = *(const float4*)(f + gr1); }
    else if (grp == 1) { pa0 = *(const float4*)(k + gr0); pa1 = *(const float4*)(k + gr1);
                         pb0 = *(const float4*)(g + gr0); pb1 = *(const float4*)(g + gr1); }
    else if (grp == 2) { pa0 = *(const float4*)(q + gr0); pa1 = *(const float4*)(q + gr1); }
    else               { pa0 = *(const float4*)(v + gc);  pb0 = *(const float4*)(g + gc); }

    // state: 4 rows x 2 cols = 4 packed f32x2 (row pairs)
    u64 M0 = 0ull, M1 = 0ull, M2 = 0ull, M3 = 0ull;

    for (int ch = 0; ch < NC; ch++) {
        const int par = ch & 1;
        __syncthreads();   // prev compute done: tiles free, partials[1-par] complete
        // ---- reduce prev chunk's partials -> gmem (1 output per thread) ----
        if (ch > 0) {
            const float* pb = smp + PT + (1 - par) * PT_PAR;
            const int s2 = tid >> 6, col = tid & 63;
            const float* p = pb + s2 * 1088 + col;
            float a0 = 0.f, a1 = 0.f, a2 = 0.f, a3 = 0.f;
#pragma unroll
            for (int rp = 0; rp < 16; rp += 4) {
                a0 += p[rp * 68];
                a1 += p[(rp + 1) * 68];
                a2 += p[(rp + 2) * 68];
                a3 += p[(rp + 3) * 68];
            }
            out[base0 + (long)(ch - 1) * S_ * HD + (long)s2 * HD + colbase + col]
                = (a0 + a1) + (a2 + a3);
        }
        // ---- stage prefetched regs -> smem tiles ----
        if (grp == 0) {
            *(float4*)(smp + FS + sb0) = pa0;
            *(float4*)(smp + FS + sb1) = pa1;
        } else if (grp == 1) {
            float4 kg0, kg1;
            kg0.x = pa0.x * pb0.x; kg0.y = pa0.y * pb0.y;
            kg0.z = pa0.z * pb0.z; kg0.w = pa0.w * pb0.w;
            kg1.x = pa1.x * pb1.x; kg1.y = pa1.y * pb1.y;
            kg1.z = pa1.z * pb1.z; kg1.w = pa1.w * pb1.w;
            *(float4*)(smp + KS + sb0) = kg0;
            *(float4*)(smp + KS + sb1) = kg1;
        } else if (grp == 2) {
            *(float4*)(smp + QS + sb0) = pa0;
            *(float4*)(smp + QS + sb1) = pa1;
        } else {
            float4 vg;
            vg.x = pa0.x * pb0.x; vg.y = pa0.y * pb0.y;
            vg.z = pa0.z * pb0.z; vg.w = pa0.w * pb0.w;
            *(float4*)(smp + VG + cidx) = vg;
        }
        __syncthreads();
        // ---- prefetch next chunk (latency overlaps compute) ----
        if (ch + 1 < NC) {
            const long off = (long)(ch + 1) * S_ * HD;
            if (grp == 0)      { pa0 = *(const float4*)(f + gr0 + off); pa1 = *(const float4*)(f + gr1 + off); }
            else if (grp == 1) { pa0 = *(const float4*)(k + gr0 + off); pa1 = *(const float4*)(k + gr1 + off);
                                 pb0 = *(const float4*)(g + gr0 + off); pb1 = *(const float4*)(g + gr1 + off); }
            else if (grp == 2) { pa0 = *(const float4*)(q + gr0 + off); pa1 = *(const float4*)(q + gr1 + off); }
            else               { pa0 = *(const float4*)(v + gc + off);  pb0 = *(const float4*)(g + gc + off); }
        }
        // ---- compute 16 steps ----
        float* pw = smp + PT + par * PT_PAR + rp68 + C0;
#pragma unroll
        for (int s = 0; s < S_; s++) {
            const ulonglong2 f2 = *(const ulonglong2*)(smp + FS + s * 128 + R0);
            const ulonglong2 k2 = *(const ulonglong2*)(smp + KS + s * 128 + R0);
            const ulonglong2 q2 = *(const ulonglong2*)(smp + QS + s * 128 + R0);
            const float2 fc = *(const float2*)(smp + FS + s * 128 + FCI);
            const float2 vg = *(const float2*)(smp + VG + s * 64 + C0);
            // column 0
            {
                const u64 fj = pk2(fc.x, fc.x), vj = pk2(vg.x, vg.x);
                u64 fo = max2c(mul2(f2.x, fj), 0.8f);
                M0 = fma2(M0, fo, mul2(k2.x, vj));
                fo = max2c(mul2(f2.y, fj), 0.8f);
                M1 = fma2(M1, fo, mul2(k2.y, vj));
            }
            // column 1
            {
                const u64 fj = pk2(fc.y, fc.y), vj = pk2(vg.y, vg.y);
                u64 fo = max2c(mul2(f2.x, fj), 0.8f);
                M2 = fma2(M2, fo, mul2(k2.x, vj));
                fo = max2c(mul2(f2.y, fj), 0.8f);
                M3 = fma2(M3, fo, mul2(k2.y, vj));
            }
            u64 o0 = mul2(q2.x, M0); o0 = fma2(q2.y, M1, o0);
            u64 o1 = mul2(q2.x, M2); o1 = fma2(q2.y, M3, o1);
            const float2 a = up2(o0), b2 = up2(o1);
            u64 oP = pk2(a.x + a.y, b2.x + b2.y);
            oP = add2(oP, shflx8(oP));   // combine lr pairs (0,1),(2,3)
            if (stsOK) *(u64*)(pw + s * 1088) = oP;   // STS.64
        }
    }
    // ---- drain: reduce final chunk's partials ----
    __syncthreads();
    {
        const float* pb = smp + PT + ((NC - 1) & 1) * PT_PAR;
        const int s2 = tid >> 6, col = tid & 63;
        const float* p = pb + s2 * 1088 + col;
        float a0 = 0.f, a1 = 0.f, a2 = 0.f, a3 = 0.f;
#pragma unroll
        for (int rp = 0; rp < 16; rp += 4) {
            a0 += p[rp * 68];
            a1 += p[(rp + 1) * 68];
            a2 += p[(rp + 2) * 68];
            a3 += p[(rp + 3) * 68];
        }
        out[base0 + (long)(NC - 1) * S_ * HD + (long)s2 * HD + colbase + col]
            = (a0 + a1) + (a2 + a3);
    }
}

extern "C" void kernel_launch(void* const* d_in, const int* in_sizes, int n_in,
                              void* d_out, int out_size) {
    const float* q = (const float*)d_in[0];
    const float* k = (const float*)d_in[1];
    const float* v = (const float*)d_in[2];
    const float* f = (const float*)d_in[3];
    const float* g = (const float*)d_in[4];
    cudaFuncSetAttribute(delta_kernel,
                         cudaFuncAttributeMaxDynamicSharedMemorySize, SM_BYTES);
    dim3 grid(2, H_, B_);
    delta_kernel<<<grid, 1024, SM_BYTES>>>(q, k, v, f, g, (float*)d_out);
}